// round 6
// baseline (speedup 1.0000x reference)
#include <cuda_runtime.h>
#include <math_constants.h>
#include <cstdint>

#define BATCH   2
#define S_LEN   2048
#define D_MODEL 1024
#define NH      16
#define HDIM    64

// ---------------- scratch ----------------------------------------------------
__device__ float g_q[BATCH * NH * S_LEN * HDIM];     // [B,H,S,64]
__device__ float g_k[BATCH * NH * S_LEN * HDIM];
__device__ float g_v[BATCH * NH * S_LEN * HDIM];
__device__ float g_att[BATCH * S_LEN * D_MODEL];     // [B,S,H*64]

// ---------------- 3xTF32 mma.sync GEMM ----------------------------------------
// C[4096,1024] = A[4096,1024] @ W[1024,1024] + bias
// CTA 128x128, BK=32, 8 warps (2x4), warp tile 64x32, mma.m16n8k8.tf32,
// error-compensated: a*b ~= ah*bh + al*bh + ah*bl  (fp32-grade accuracy).
#define BM 128
#define BN 128
#define BK 32

__device__ __forceinline__ void mma_tf32(float c[4], const uint32_t a[4],
                                         const uint32_t b[2]) {
    asm volatile(
        "mma.sync.aligned.m16n8k8.row.col.f32.tf32.tf32.f32 "
        "{%0,%1,%2,%3}, {%4,%5,%6,%7}, {%8,%9}, {%0,%1,%2,%3};\n"
        : "+f"(c[0]), "+f"(c[1]), "+f"(c[2]), "+f"(c[3])
        : "r"(a[0]), "r"(a[1]), "r"(a[2]), "r"(a[3]), "r"(b[0]), "r"(b[1]));
}

__device__ __forceinline__ uint32_t f2tf32(float x) {
    uint32_t r;
    asm("cvt.rna.tf32.f32 %0, %1;" : "=r"(r) : "f"(x));
    return r;
}
// split fp32 -> (hi tf32, lo tf32) with x ~= hi + lo
__device__ __forceinline__ void tf32_split(float x, uint32_t& hi, uint32_t& lo) {
    hi = f2tf32(x);
    lo = f2tf32(x - __uint_as_float(hi));
}

// MODE 0: row-major out. MODE 1: scatter to [B,H,S,64]
template <int MODE>
__device__ __forceinline__ void gemm_mma_body(const float* __restrict__ A,
                                              const float* __restrict__ W,
                                              const float* __restrict__ bias,
                                              float* __restrict__ C)
{
    __shared__ float As[BK][BM + 4];   // As[k][m]
    __shared__ float Bs[BK][BN + 4];   // Bs[k][n]

    const int tid  = threadIdx.x;
    const int wid  = tid >> 5;
    const int lane = tid & 31;
    const int g    = lane >> 2;     // group id 0..7
    const int t    = lane & 3;      // thread-in-group 0..3
    const int wm   = wid >> 2;      // 0..1  (m: 64 each)
    const int wn   = wid & 3;       // 0..3  (n: 32 each)
    const int bm   = blockIdx.y * BM;
    const int bn   = blockIdx.x * BN;

    float c[4][4][4];               // [m-tile][n-tile][frag]
#pragma unroll
    for (int i = 0; i < 4; i++)
#pragma unroll
        for (int j = 0; j < 4; j++)
#pragma unroll
            for (int f = 0; f < 4; f++) c[i][j][f] = 0.f;

    const int a_m = tid >> 3;            // 0..31 (+32/pass)
    const int a_k = (tid & 7) << 2;      // 0,4,...,28
    const int b_k = tid >> 5;            // 0..7  (+8/pass)
    const int b_n = (tid & 31) << 2;     // 0..124

    for (int k0 = 0; k0 < D_MODEL; k0 += BK) {
        // stage A transposed: As[k][m] = A[bm+m][k0+k]
#pragma unroll
        for (int p = 0; p < 4; p++) {
            const int m = a_m + p * 32;
            float4 v = *(const float4*)(A + (size_t)(bm + m) * D_MODEL + k0 + a_k);
            As[a_k + 0][m] = v.x;
            As[a_k + 1][m] = v.y;
            As[a_k + 2][m] = v.z;
            As[a_k + 3][m] = v.w;
        }
        // stage B: Bs[k][n] = W[k0+k][bn+n]
#pragma unroll
        for (int p = 0; p < 4; p++) {
            const int k = b_k + p * 8;
            *(float4*)&Bs[k][b_n] =
                *(const float4*)(W + (size_t)(k0 + k) * D_MODEL + bn + b_n);
        }
        __syncthreads();

#pragma unroll
        for (int s = 0; s < 4; s++) {
            const int kk = s * 8;
            uint32_t ah[4][4], al[4][4], bh[4][2], bl[4][2];
#pragma unroll
            for (int i = 0; i < 4; i++) {
                const int mb = wm * 64 + i * 16;
                tf32_split(As[kk + t    ][mb + g    ], ah[i][0], al[i][0]);
                tf32_split(As[kk + t    ][mb + g + 8], ah[i][1], al[i][1]);
                tf32_split(As[kk + t + 4][mb + g    ], ah[i][2], al[i][2]);
                tf32_split(As[kk + t + 4][mb + g + 8], ah[i][3], al[i][3]);
            }
#pragma unroll
            for (int j = 0; j < 4; j++) {
                const int nb = wn * 32 + j * 8;
                tf32_split(Bs[kk + t    ][nb + g], bh[j][0], bl[j][0]);
                tf32_split(Bs[kk + t + 4][nb + g], bh[j][1], bl[j][1]);
            }
#pragma unroll
            for (int i = 0; i < 4; i++)
#pragma unroll
                for (int j = 0; j < 4; j++) {
                    mma_tf32(c[i][j], al[i], bh[j]);   // lo*hi correction
                    mma_tf32(c[i][j], ah[i], bl[j]);   // hi*lo correction
                    mma_tf32(c[i][j], ah[i], bh[j]);   // main term last (largest)
                }
        }
        __syncthreads();
    }

    // epilogue: c0,c1 -> (row, col..col+1); c2,c3 -> (row+8, col..col+1)
#pragma unroll
    for (int i = 0; i < 4; i++) {
#pragma unroll
        for (int j = 0; j < 4; j++) {
            const int col = bn + wn * 32 + j * 8 + 2 * t;
            const float bx = bias[col], by = bias[col + 1];
#pragma unroll
            for (int h2 = 0; h2 < 2; h2++) {
                const int row = bm + wm * 64 + i * 16 + g + h2 * 8;
                float2 o;
                o.x = c[i][j][h2 * 2 + 0] + bx;
                o.y = c[i][j][h2 * 2 + 1] + by;
                if (MODE == 0) {
                    *(float2*)(C + (size_t)row * D_MODEL + col) = o;
                } else {
                    const int b_ = row >> 11, s_ = row & (S_LEN - 1);
                    const int h_ = col >> 6,  d_ = col & 63;
                    *(float2*)(C + (((size_t)b_ * NH + h_) * S_LEN + s_) * HDIM + d_) = o;
                }
            }
        }
    }
}

__global__ __launch_bounds__(256) void gemm_qkv_mma(
    const float* __restrict__ x,
    const float* __restrict__ Wq, const float* __restrict__ bq,
    const float* __restrict__ Wk, const float* __restrict__ bk,
    const float* __restrict__ Wv, const float* __restrict__ bv)
{
    const float* W; const float* bias; float* out;
    if (blockIdx.z == 0)      { W = Wq; bias = bq; out = g_q; }
    else if (blockIdx.z == 1) { W = Wk; bias = bk; out = g_k; }
    else                      { W = Wv; bias = bv; out = g_v; }
    gemm_mma_body<1>(x, W, bias, out);
}

__global__ __launch_bounds__(256) void gemm_out_mma(
    const float* __restrict__ Wo, const float* __restrict__ bo,
    float* __restrict__ out)
{
    gemm_mma_body<0>(g_att, Wo, bo, out);
}

// ---------------- flash attention (unchanged from passing R2) ----------------
#define FBR 128
#define FBC 32
#define FLASH_SMEM_BYTES ((64 * 128 + 64 * FBC + FBC * 64 + FBC) * 4)

__global__ __launch_bounds__(128) void flash_kernel(const unsigned char* __restrict__ mask)
{
    extern __shared__ float fsm[];
    float* qst = fsm;
    float* Kst = fsm + 64 * 128;
    float* Vs  = fsm + 64 * 128 + 64 * FBC;
    int*   maskS = (int*)(fsm + 64 * 128 + 64 * FBC + FBC * 64);

    const int tid = threadIdx.x;
    const int qt  = (gridDim.x - 1) - blockIdx.x;
    const int h   = blockIdx.y;
    const int b   = blockIdx.z;
    const size_t bh = (size_t)b * NH + h;
    const float* qb = g_q + bh * S_LEN * HDIM;
    const float* kb = g_k + bh * S_LEN * HDIM;
    const float* vb = g_v + bh * S_LEN * HDIM;

#pragma unroll
    for (int p = 0; p < 16; p++) {
        const int idx = p * 128 + tid;
        const int row = idx >> 4;
        const int d4  = (idx & 15) << 2;
        float4 qv = *(const float4*)(qb + (size_t)(qt * FBR + row) * HDIM + d4);
        qst[(d4 + 0) * 128 + row] = qv.x;
        qst[(d4 + 1) * 128 + row] = qv.y;
        qst[(d4 + 2) * 128 + row] = qv.z;
        qst[(d4 + 3) * 128 + row] = qv.w;
    }

    float acc[HDIM];
#pragma unroll
    for (int d = 0; d < HDIM; d++) acc[d] = 0.f;
    float mrow = -CUDART_INF_F;
    float lrow = 0.f;

    const int row_g = qt * FBR + tid;
    const int nkt   = (qt + 1) * (FBR / FBC);
    const int diag0 = qt * (FBR / FBC);

    for (int kt = 0; kt < nkt; kt++) {
        __syncthreads();
#pragma unroll
        for (int p = 0; p < 4; p++) {
            const int idx = p * 128 + tid;
            const int j   = idx >> 4;
            const int d4  = (idx & 15) << 2;
            const size_t goff = (size_t)(kt * FBC + j) * HDIM + d4;
            float4 kv = *(const float4*)(kb + goff);
            Kst[(d4 + 0) * FBC + j] = kv.x;
            Kst[(d4 + 1) * FBC + j] = kv.y;
            Kst[(d4 + 2) * FBC + j] = kv.z;
            Kst[(d4 + 3) * FBC + j] = kv.w;
            *(float4*)(Vs + j * HDIM + d4) = *(const float4*)(vb + goff);
        }
        if (tid < FBC) maskS[tid] = mask[(size_t)b * S_LEN + kt * FBC + tid];
        __syncthreads();

        float s[FBC];
#pragma unroll
        for (int j = 0; j < FBC; j++) s[j] = 0.f;
#pragma unroll 4
        for (int d = 0; d < HDIM; d++) {
            const float qd = qst[d * 128 + tid];
#pragma unroll
            for (int j4 = 0; j4 < 8; j4++) {
                float4 kk = *(float4*)(Kst + d * FBC + j4 * 4);
                s[j4 * 4 + 0] = fmaf(qd, kk.x, s[j4 * 4 + 0]);
                s[j4 * 4 + 1] = fmaf(qd, kk.y, s[j4 * 4 + 1]);
                s[j4 * 4 + 2] = fmaf(qd, kk.z, s[j4 * 4 + 2]);
                s[j4 * 4 + 3] = fmaf(qd, kk.w, s[j4 * 4 + 3]);
            }
        }

        float mt = mrow;
        const bool need_causal = (kt >= diag0);
#pragma unroll
        for (int j = 0; j < FBC; j++) {
            float sv = s[j] * 0.125f;
            if ((need_causal && (kt * FBC + j > row_g)) || maskS[j])
                sv = -CUDART_INF_F;
            s[j] = sv;
            mt = fmaxf(mt, sv);
        }

        if (mt > -CUDART_INF_F) {
            const float scale = (mrow > -CUDART_INF_F) ? __expf(mrow - mt) : 0.f;
            mrow = mt;
            float psum = 0.f;
#pragma unroll
            for (int j = 0; j < FBC; j++) {
                const float p = __expf(s[j] - mt);
                s[j] = p;
                psum += p;
            }
            lrow = lrow * scale + psum;
#pragma unroll
            for (int d = 0; d < HDIM; d++) acc[d] *= scale;
#pragma unroll
            for (int j = 0; j < FBC; j++) {
                const float pj = s[j];
#pragma unroll
                for (int d4 = 0; d4 < 16; d4++) {
                    float4 vv = *(float4*)(Vs + j * HDIM + d4 * 4);
                    acc[d4 * 4 + 0] = fmaf(pj, vv.x, acc[d4 * 4 + 0]);
                    acc[d4 * 4 + 1] = fmaf(pj, vv.y, acc[d4 * 4 + 1]);
                    acc[d4 * 4 + 2] = fmaf(pj, vv.z, acc[d4 * 4 + 2]);
                    acc[d4 * 4 + 3] = fmaf(pj, vv.w, acc[d4 * 4 + 3]);
                }
            }
        }
    }

    const float inv = 1.f / lrow;
    float* op = g_att + ((size_t)b * S_LEN + row_g) * D_MODEL + h * HDIM;
#pragma unroll
    for (int d4 = 0; d4 < 16; d4++) {
        float4 w;
        w.x = acc[d4 * 4 + 0] * inv;
        w.y = acc[d4 * 4 + 1] * inv;
        w.z = acc[d4 * 4 + 2] * inv;
        w.w = acc[d4 * 4 + 3] * inv;
        *(float4*)(op + d4 * 4) = w;
    }
}

// ---------------- launch ------------------------------------------------------
extern "C" void kernel_launch(void* const* d_in, const int* in_sizes, int n_in,
                              void* d_out, int out_size)
{
    const float* x  = (const float*)d_in[0];
    const unsigned char* mask = (const unsigned char*)d_in[1];
    const float* Wq = (const float*)d_in[2];
    const float* bq = (const float*)d_in[3];
    const float* Wk = (const float*)d_in[4];
    const float* bk = (const float*)d_in[5];
    const float* Wv = (const float*)d_in[6];
    const float* bv = (const float*)d_in[7];
    const float* Wo = (const float*)d_in[8];
    const float* bo = (const float*)d_in[9];
    float* out = (float*)d_out;

    cudaFuncSetAttribute(flash_kernel,
                         cudaFuncAttributeMaxDynamicSharedMemorySize,
                         FLASH_SMEM_BYTES);

    // 1) QKV projections (3xTF32 mma.sync)
    dim3 gq(D_MODEL / BN, (BATCH * S_LEN) / BM, 3);
    gemm_qkv_mma<<<gq, 256>>>(x, Wq, bq, Wk, bk, Wv, bv);

    // 2) causal flash attention
    dim3 gf(S_LEN / FBR, NH, BATCH);
    flash_kernel<<<gf, 128, FLASH_SMEM_BYTES>>>(mask);

    // 3) output projection (3xTF32 mma.sync)
    dim3 go(D_MODEL / BN, (BATCH * S_LEN) / BM, 1);
    gemm_out_mma<<<go, 256>>>(Wo, bo, out);
}

// round 7
// speedup vs baseline: 1.0028x; 1.0028x over previous
#include <cuda_runtime.h>
#include <math_constants.h>
#include <cstdint>

#define BATCH   2
#define S_LEN   2048
#define D_MODEL 1024
#define NH      16
#define HDIM    64

// ---------------- scratch ----------------------------------------------------
__device__ float g_q[BATCH * NH * S_LEN * HDIM];     // [B,H,S,64]
__device__ float g_k[BATCH * NH * S_LEN * HDIM];
__device__ float g_v[BATCH * NH * S_LEN * HDIM];
__device__ float g_att[BATCH * S_LEN * D_MODEL];     // [B,S,H*64]

// ---------------- 3xTF32 mma.sync GEMM ----------------------------------------
// C[4096,1024] = A[4096,1024] @ W[1024,1024] + bias
// CTA 128x128, BK=32, 8 warps (2x4), warp tile 64x32, mma.m16n8k8.tf32,
// error-compensated: a*b ~= ah*bh + al*bh + ah*bl  (fp32-grade accuracy).
#define BM 128
#define BN 128
#define BK 32

__device__ __forceinline__ void mma_tf32(float c[4], const uint32_t a[4],
                                         const uint32_t b[2]) {
    asm volatile(
        "mma.sync.aligned.m16n8k8.row.col.f32.tf32.tf32.f32 "
        "{%0,%1,%2,%3}, {%4,%5,%6,%7}, {%8,%9}, {%0,%1,%2,%3};\n"
        : "+f"(c[0]), "+f"(c[1]), "+f"(c[2]), "+f"(c[3])
        : "r"(a[0]), "r"(a[1]), "r"(a[2]), "r"(a[3]), "r"(b[0]), "r"(b[1]));
}

__device__ __forceinline__ uint32_t f2tf32(float x) {
    uint32_t r;
    asm("cvt.rna.tf32.f32 %0, %1;" : "=r"(r) : "f"(x));
    return r;
}
// split fp32 -> (hi tf32, lo tf32) with x ~= hi + lo
__device__ __forceinline__ void tf32_split(float x, uint32_t& hi, uint32_t& lo) {
    hi = f2tf32(x);
    lo = f2tf32(x - __uint_as_float(hi));
}

// MODE 0: row-major out. MODE 1: scatter to [B,H,S,64]
template <int MODE>
__device__ __forceinline__ void gemm_mma_body(const float* __restrict__ A,
                                              const float* __restrict__ W,
                                              const float* __restrict__ bias,
                                              float* __restrict__ C)
{
    __shared__ float As[BK][BM + 4];   // As[k][m]
    __shared__ float Bs[BK][BN + 4];   // Bs[k][n]

    const int tid  = threadIdx.x;
    const int wid  = tid >> 5;
    const int lane = tid & 31;
    const int g    = lane >> 2;     // group id 0..7
    const int t    = lane & 3;      // thread-in-group 0..3
    const int wm   = wid >> 2;      // 0..1  (m: 64 each)
    const int wn   = wid & 3;       // 0..3  (n: 32 each)
    const int bm   = blockIdx.y * BM;
    const int bn   = blockIdx.x * BN;

    float c[4][4][4];               // [m-tile][n-tile][frag]
#pragma unroll
    for (int i = 0; i < 4; i++)
#pragma unroll
        for (int j = 0; j < 4; j++)
#pragma unroll
            for (int f = 0; f < 4; f++) c[i][j][f] = 0.f;

    const int a_m = tid >> 3;            // 0..31 (+32/pass)
    const int a_k = (tid & 7) << 2;      // 0,4,...,28
    const int b_k = tid >> 5;            // 0..7  (+8/pass)
    const int b_n = (tid & 31) << 2;     // 0..124

    for (int k0 = 0; k0 < D_MODEL; k0 += BK) {
        // stage A transposed: As[k][m] = A[bm+m][k0+k]
#pragma unroll
        for (int p = 0; p < 4; p++) {
            const int m = a_m + p * 32;
            float4 v = *(const float4*)(A + (size_t)(bm + m) * D_MODEL + k0 + a_k);
            As[a_k + 0][m] = v.x;
            As[a_k + 1][m] = v.y;
            As[a_k + 2][m] = v.z;
            As[a_k + 3][m] = v.w;
        }
        // stage B: Bs[k][n] = W[k0+k][bn+n]
#pragma unroll
        for (int p = 0; p < 4; p++) {
            const int k = b_k + p * 8;
            *(float4*)&Bs[k][b_n] =
                *(const float4*)(W + (size_t)(k0 + k) * D_MODEL + bn + b_n);
        }
        __syncthreads();

#pragma unroll
        for (int s = 0; s < 4; s++) {
            const int kk = s * 8;
            uint32_t ah[4][4], al[4][4], bh[4][2], bl[4][2];
#pragma unroll
            for (int i = 0; i < 4; i++) {
                const int mb = wm * 64 + i * 16;
                tf32_split(As[kk + t    ][mb + g    ], ah[i][0], al[i][0]);
                tf32_split(As[kk + t    ][mb + g + 8], ah[i][1], al[i][1]);
                tf32_split(As[kk + t + 4][mb + g    ], ah[i][2], al[i][2]);
                tf32_split(As[kk + t + 4][mb + g + 8], ah[i][3], al[i][3]);
            }
#pragma unroll
            for (int j = 0; j < 4; j++) {
                const int nb = wn * 32 + j * 8;
                tf32_split(Bs[kk + t    ][nb + g], bh[j][0], bl[j][0]);
                tf32_split(Bs[kk + t + 4][nb + g], bh[j][1], bl[j][1]);
            }
#pragma unroll
            for (int i = 0; i < 4; i++)
#pragma unroll
                for (int j = 0; j < 4; j++) {
                    mma_tf32(c[i][j], al[i], bh[j]);   // lo*hi correction
                    mma_tf32(c[i][j], ah[i], bl[j]);   // hi*lo correction
                    mma_tf32(c[i][j], ah[i], bh[j]);   // main term last (largest)
                }
        }
        __syncthreads();
    }

    // epilogue: c0,c1 -> (row, col..col+1); c2,c3 -> (row+8, col..col+1)
#pragma unroll
    for (int i = 0; i < 4; i++) {
#pragma unroll
        for (int j = 0; j < 4; j++) {
            const int col = bn + wn * 32 + j * 8 + 2 * t;
            const float bx = bias[col], by = bias[col + 1];
#pragma unroll
            for (int h2 = 0; h2 < 2; h2++) {
                const int row = bm + wm * 64 + i * 16 + g + h2 * 8;
                float2 o;
                o.x = c[i][j][h2 * 2 + 0] + bx;
                o.y = c[i][j][h2 * 2 + 1] + by;
                if (MODE == 0) {
                    *(float2*)(C + (size_t)row * D_MODEL + col) = o;
                } else {
                    const int b_ = row >> 11, s_ = row & (S_LEN - 1);
                    const int h_ = col >> 6,  d_ = col & 63;
                    *(float2*)(C + (((size_t)b_ * NH + h_) * S_LEN + s_) * HDIM + d_) = o;
                }
            }
        }
    }
}

__global__ __launch_bounds__(256) void gemm_qkv_mma(
    const float* __restrict__ x,
    const float* __restrict__ Wq, const float* __restrict__ bq,
    const float* __restrict__ Wk, const float* __restrict__ bk,
    const float* __restrict__ Wv, const float* __restrict__ bv)
{
    const float* W; const float* bias; float* out;
    if (blockIdx.z == 0)      { W = Wq; bias = bq; out = g_q; }
    else if (blockIdx.z == 1) { W = Wk; bias = bk; out = g_k; }
    else                      { W = Wv; bias = bv; out = g_v; }
    gemm_mma_body<1>(x, W, bias, out);
}

__global__ __launch_bounds__(256) void gemm_out_mma(
    const float* __restrict__ Wo, const float* __restrict__ bo,
    float* __restrict__ out)
{
    gemm_mma_body<0>(g_att, Wo, bo, out);
}

// ---------------- flash attention (unchanged from passing R2) ----------------
#define FBR 128
#define FBC 32
#define FLASH_SMEM_BYTES ((64 * 128 + 64 * FBC + FBC * 64 + FBC) * 4)

__global__ __launch_bounds__(128) void flash_kernel(const unsigned char* __restrict__ mask)
{
    extern __shared__ float fsm[];
    float* qst = fsm;
    float* Kst = fsm + 64 * 128;
    float* Vs  = fsm + 64 * 128 + 64 * FBC;
    int*   maskS = (int*)(fsm + 64 * 128 + 64 * FBC + FBC * 64);

    const int tid = threadIdx.x;
    const int qt  = (gridDim.x - 1) - blockIdx.x;
    const int h   = blockIdx.y;
    const int b   = blockIdx.z;
    const size_t bh = (size_t)b * NH + h;
    const float* qb = g_q + bh * S_LEN * HDIM;
    const float* kb = g_k + bh * S_LEN * HDIM;
    const float* vb = g_v + bh * S_LEN * HDIM;

#pragma unroll
    for (int p = 0; p < 16; p++) {
        const int idx = p * 128 + tid;
        const int row = idx >> 4;
        const int d4  = (idx & 15) << 2;
        float4 qv = *(const float4*)(qb + (size_t)(qt * FBR + row) * HDIM + d4);
        qst[(d4 + 0) * 128 + row] = qv.x;
        qst[(d4 + 1) * 128 + row] = qv.y;
        qst[(d4 + 2) * 128 + row] = qv.z;
        qst[(d4 + 3) * 128 + row] = qv.w;
    }

    float acc[HDIM];
#pragma unroll
    for (int d = 0; d < HDIM; d++) acc[d] = 0.f;
    float mrow = -CUDART_INF_F;
    float lrow = 0.f;

    const int row_g = qt * FBR + tid;
    const int nkt   = (qt + 1) * (FBR / FBC);
    const int diag0 = qt * (FBR / FBC);

    for (int kt = 0; kt < nkt; kt++) {
        __syncthreads();
#pragma unroll
        for (int p = 0; p < 4; p++) {
            const int idx = p * 128 + tid;
            const int j   = idx >> 4;
            const int d4  = (idx & 15) << 2;
            const size_t goff = (size_t)(kt * FBC + j) * HDIM + d4;
            float4 kv = *(const float4*)(kb + goff);
            Kst[(d4 + 0) * FBC + j] = kv.x;
            Kst[(d4 + 1) * FBC + j] = kv.y;
            Kst[(d4 + 2) * FBC + j] = kv.z;
            Kst[(d4 + 3) * FBC + j] = kv.w;
            *(float4*)(Vs + j * HDIM + d4) = *(const float4*)(vb + goff);
        }
        if (tid < FBC) maskS[tid] = mask[(size_t)b * S_LEN + kt * FBC + tid];
        __syncthreads();

        float s[FBC];
#pragma unroll
        for (int j = 0; j < FBC; j++) s[j] = 0.f;
#pragma unroll 4
        for (int d = 0; d < HDIM; d++) {
            const float qd = qst[d * 128 + tid];
#pragma unroll
            for (int j4 = 0; j4 < 8; j4++) {
                float4 kk = *(float4*)(Kst + d * FBC + j4 * 4);
                s[j4 * 4 + 0] = fmaf(qd, kk.x, s[j4 * 4 + 0]);
                s[j4 * 4 + 1] = fmaf(qd, kk.y, s[j4 * 4 + 1]);
                s[j4 * 4 + 2] = fmaf(qd, kk.z, s[j4 * 4 + 2]);
                s[j4 * 4 + 3] = fmaf(qd, kk.w, s[j4 * 4 + 3]);
            }
        }

        float mt = mrow;
        const bool need_causal = (kt >= diag0);
#pragma unroll
        for (int j = 0; j < FBC; j++) {
            float sv = s[j] * 0.125f;
            if ((need_causal && (kt * FBC + j > row_g)) || maskS[j])
                sv = -CUDART_INF_F;
            s[j] = sv;
            mt = fmaxf(mt, sv);
        }

        if (mt > -CUDART_INF_F) {
            const float scale = (mrow > -CUDART_INF_F) ? __expf(mrow - mt) : 0.f;
            mrow = mt;
            float psum = 0.f;
#pragma unroll
            for (int j = 0; j < FBC; j++) {
                const float p = __expf(s[j] - mt);
                s[j] = p;
                psum += p;
            }
            lrow = lrow * scale + psum;
#pragma unroll
            for (int d = 0; d < HDIM; d++) acc[d] *= scale;
#pragma unroll
            for (int j = 0; j < FBC; j++) {
                const float pj = s[j];
#pragma unroll
                for (int d4 = 0; d4 < 16; d4++) {
                    float4 vv = *(float4*)(Vs + j * HDIM + d4 * 4);
                    acc[d4 * 4 + 0] = fmaf(pj, vv.x, acc[d4 * 4 + 0]);
                    acc[d4 * 4 + 1] = fmaf(pj, vv.y, acc[d4 * 4 + 1]);
                    acc[d4 * 4 + 2] = fmaf(pj, vv.z, acc[d4 * 4 + 2]);
                    acc[d4 * 4 + 3] = fmaf(pj, vv.w, acc[d4 * 4 + 3]);
                }
            }
        }
    }

    const float inv = 1.f / lrow;
    float* op = g_att + ((size_t)b * S_LEN + row_g) * D_MODEL + h * HDIM;
#pragma unroll
    for (int d4 = 0; d4 < 16; d4++) {
        float4 w;
        w.x = acc[d4 * 4 + 0] * inv;
        w.y = acc[d4 * 4 + 1] * inv;
        w.z = acc[d4 * 4 + 2] * inv;
        w.w = acc[d4 * 4 + 3] * inv;
        *(float4*)(op + d4 * 4) = w;
    }
}

// ---------------- launch ------------------------------------------------------
extern "C" void kernel_launch(void* const* d_in, const int* in_sizes, int n_in,
                              void* d_out, int out_size)
{
    const float* x  = (const float*)d_in[0];
    const unsigned char* mask = (const unsigned char*)d_in[1];
    const float* Wq = (const float*)d_in[2];
    const float* bq = (const float*)d_in[3];
    const float* Wk = (const float*)d_in[4];
    const float* bk = (const float*)d_in[5];
    const float* Wv = (const float*)d_in[6];
    const float* bv = (const float*)d_in[7];
    const float* Wo = (const float*)d_in[8];
    const float* bo = (const float*)d_in[9];
    float* out = (float*)d_out;

    cudaFuncSetAttribute(flash_kernel,
                         cudaFuncAttributeMaxDynamicSharedMemorySize,
                         FLASH_SMEM_BYTES);

    // 1) QKV projections (3xTF32 mma.sync)
    dim3 gq(D_MODEL / BN, (BATCH * S_LEN) / BM, 3);
    gemm_qkv_mma<<<gq, 256>>>(x, Wq, bq, Wk, bk, Wv, bv);

    // 2) causal flash attention
    dim3 gf(S_LEN / FBR, NH, BATCH);
    flash_kernel<<<gf, 128, FLASH_SMEM_BYTES>>>(mask);

    // 3) output projection (3xTF32 mma.sync)
    dim3 go(D_MODEL / BN, (BATCH * S_LEN) / BM, 1);
    gemm_out_mma<<<go, 256>>>(Wo, bo, out);
}